// round 2
// baseline (speedup 1.0000x reference)
#include <cuda_runtime.h>
#include <cstdint>

// Problem: cosine K-Means EM step. N=1e6 (from in_sizes), d=64, K=256.
#define KC 256
#define DIM 64
#define TPB 512
#define NBLK 148   // one persistent block per SM (129KB smem/block)

// Scratch (allocation-free rule: __device__ globals)
__device__ float g_sums[KC * DIM];
__device__ int   g_counts[KC];
__device__ float g_J;

// ---------- IEEE helpers (immune to --use_fast_math) ----------
__device__ __forceinline__ float fdiv_rn(float a, float b) {
    float r; asm("div.rn.f32 %0, %1, %2;" : "=f"(r) : "f"(a), "f"(b)); return r;
}
__device__ __forceinline__ float fsqrt_rn(float a) {
    float r; asm("sqrt.rn.f32 %0, %1;" : "=f"(r) : "f"(a)); return r;
}

// ---------- packed f32x2 helpers (sm_100+) ----------
typedef unsigned long long u64;

__device__ __forceinline__ u64 ffma2(u64 a, u64 b, u64 c) {
    u64 r; asm("fma.rn.f32x2 %0, %1, %2, %3;" : "=l"(r) : "l"(a), "l"(b), "l"(c)); return r;
}
__device__ __forceinline__ u64 fmul2(u64 a, u64 b) {
    u64 r; asm("mul.rn.f32x2 %0, %1, %2;" : "=l"(r) : "l"(a), "l"(b)); return r;
}
__device__ __forceinline__ u64 fadd2(u64 a, u64 b) {
    u64 r; asm("add.rn.f32x2 %0, %1, %2;" : "=l"(r) : "l"(a), "l"(b)); return r;
}
__device__ __forceinline__ u64 pack2(float lo, float hi) {
    u64 r; asm("mov.b64 %0, {%1, %2};" : "=l"(r) : "f"(lo), "f"(hi)); return r;
}
__device__ __forceinline__ void unpack2(u64 v, float& lo, float& hi) {
    asm("mov.b64 {%0, %1}, %2;" : "=f"(lo), "=f"(hi) : "l"(v));
}

// ---------- kernel 0: zero global scratch (runs every launch; graph-safe) ----------
__global__ void ck_zero_kernel() {
    int i = blockIdx.x * blockDim.x + threadIdx.x;
    if (i < KC * DIM) g_sums[i] = 0.0f;
    if (i < KC)       g_counts[i] = 0;
    if (i == 0)       g_J = 0.0f;
}

// ---------- kernel 1: persistent assign + local accumulate + one flush ----------
__global__ void __launch_bounds__(TPB)
ck_assign_kernel(const float* __restrict__ X,
                 const float* __restrict__ C,
                 float* __restrict__ labels_out,
                 int N) {
    extern __shared__ float smem[];
    float* sC   = smem;                 // [KC*DIM] centroids (64KB)
    float* sAcc = smem + KC * DIM;      // [KC*DIM] per-block bins (64KB, XOR-swizzled)
    __shared__ int sCnt[KC];

    const int tid = threadIdx.x;

    // Stage centroids (coalesced float4) + zero local bins
    {
        const float4* src = (const float4*)C;
        float4* dstC = (float4*)sC;
        float4* dstA = (float4*)sAcc;
        const float4 z = make_float4(0.f, 0.f, 0.f, 0.f);
        #pragma unroll
        for (int i = tid; i < (KC * DIM) / 4; i += TPB) {
            dstC[i] = src[i];
            dstA[i] = z;
        }
        if (tid < KC) sCnt[tid] = 0;
    }
    __syncthreads();

    float jsum = 0.0f;
    const long long stride = (long long)gridDim.x * TPB;

    for (long long row = (long long)blockIdx.x * TPB + tid; row < N; row += stride) {
        // Load own row as packed f32x2 (row base is 256B aligned)
        u64 x[DIM / 2];
        const ulonglong2* xr = (const ulonglong2*)(X + row * DIM);
        #pragma unroll
        for (int j = 0; j < DIM / 4; j++) {
            ulonglong2 t = xr[j];
            x[2 * j]     = t.x;
            x[2 * j + 1] = t.y;
        }

        // L2 normalize: xn = x / max(sqrt(sum(x^2)), 1e-12)
        u64 aq = 0ull;
        #pragma unroll
        for (int j = 0; j < DIM / 2; j++) aq = ffma2(x[j], x[j], aq);
        float qlo, qhi; unpack2(aq, qlo, qhi);
        float inv = fdiv_rn(1.0f, fmaxf(fsqrt_rn(qlo + qhi), 1e-12f));
        u64 inv2 = pack2(inv, inv);
        #pragma unroll
        for (int j = 0; j < DIM / 2; j++) x[j] = fmul2(x[j], inv2);

        // Argmax over 256 centroids; ascending k + strict '>' == jnp.argmax tie-break
        float best = -__int_as_float(0x7f800000);
        int   bk = 0;
        #pragma unroll 2
        for (int k = 0; k < KC; k++) {
            const ulonglong2* cr = (const ulonglong2*)(sC + k * DIM);
            u64 a0 = 0ull, a1 = 0ull, a2 = 0ull, a3 = 0ull;
            #pragma unroll
            for (int j = 0; j < DIM / 4; j++) {
                ulonglong2 c = cr[j];      // LDS.128, warp-broadcast, conflict-free
                if (j & 1) {
                    a2 = ffma2(x[2 * j],     c.x, a2);
                    a3 = ffma2(x[2 * j + 1], c.y, a3);
                } else {
                    a0 = ffma2(x[2 * j],     c.x, a0);
                    a1 = ffma2(x[2 * j + 1], c.y, a1);
                }
            }
            u64 s2 = fadd2(fadd2(a0, a1), fadd2(a2, a3));
            float slo, shi; unpack2(s2, slo, shi);
            float sim = slo + shi;
            if (sim > best) { best = sim; bk = k; }
        }

        labels_out[row] = (float)bk;
        jsum += 1.0f - best;

        // Local accumulation into XOR-swizzled bins (different labels -> different banks)
        atomicAdd(&sCnt[bk], 1);
        const int sw = bk & 31;
        float* arow = &sAcc[bk * DIM];
        #pragma unroll
        for (int j = 0; j < DIM / 2; j++) {
            float f0, f1; unpack2(x[j], f0, f1);
            atomicAdd(&arow[(2 * j)     ^ sw], f0);
            atomicAdd(&arow[(2 * j + 1) ^ sw], f1);
        }
    }

    // mean_J partial: warp reduce, one global atomic per warp
    #pragma unroll
    for (int o = 16; o > 0; o >>= 1)
        jsum += __shfl_xor_sync(0xffffffffu, jsum, o);
    if ((tid & 31) == 0) atomicAdd(&g_J, jsum);

    __syncthreads();

    // Flush: 16384 + 256 global REDs per block (un-swizzle on the way out)
    for (int i = tid; i < KC * DIM; i += TPB) {
        int k = i >> 6, js = i & 63;
        atomicAdd(&g_sums[(k << 6) + (js ^ (k & 31))], sAcc[i]);
    }
    if (tid < KC && sCnt[tid] > 0) atomicAdd(&g_counts[tid], sCnt[tid]);
}

// ---------- kernel 2: finalize centroids + mean_J ----------
__global__ void ck_finalize_kernel(const float* __restrict__ C,
                                   float* __restrict__ out,   // [KC*DIM] C_new
                                   int N) {
    int k = threadIdx.x;   // 256 threads, one per cluster
    float cnt = (float)g_counts[k];
    bool non_empty = (cnt > 0.0f);
    float safe = fmaxf(cnt, 1.0f);

    float m[DIM];
    float ss = 0.0f;
    #pragma unroll
    for (int j = 0; j < DIM; j++) {
        m[j] = fdiv_rn(g_sums[k * DIM + j], safe);
        ss = fmaf(m[j], m[j], ss);
    }
    float nrm = fmaxf(fsqrt_rn(ss), 1e-12f);
    #pragma unroll
    for (int j = 0; j < DIM; j++)
        out[k * DIM + j] = non_empty ? fdiv_rn(m[j], nrm) : C[k * DIM + j];

    if (k == 0)
        out[(size_t)KC * DIM + (size_t)N] = fdiv_rn(g_J, (float)N);
}

extern "C" void kernel_launch(void* const* d_in, const int* in_sizes, int n_in,
                              void* d_out, int out_size) {
    const float* X = (const float*)d_in[0];
    const float* C = (const float*)d_in[1];
    int N = in_sizes[0] / DIM;

    float* out = (float*)d_out;
    float* labels = out + KC * DIM;   // layout: C_new[16384], labels[N], mean_J[1]

    static const int SMEM = 2 * KC * DIM * sizeof(float);   // 128KB
    cudaFuncSetAttribute(ck_assign_kernel,
                         cudaFuncAttributeMaxDynamicSharedMemorySize, SMEM);

    ck_zero_kernel<<<(KC * DIM + 255) / 256, 256>>>();

    int blocks = (N + TPB - 1) / TPB;
    if (blocks > NBLK) blocks = NBLK;
    ck_assign_kernel<<<blocks, TPB, SMEM>>>(X, C, labels, N);

    ck_finalize_kernel<<<1, KC>>>(C, out, N);
}

// round 3
// speedup vs baseline: 1.1739x; 1.1739x over previous
#include <cuda_runtime.h>
#include <cstdint>

// Cosine K-Means EM step. N=1e6 (from in_sizes), d=64, K=256.
#define KC 256
#define DIM 64
#define TPB 256
#define NBLK 148   // one persistent block per SM (128KB dyn smem/block)

// Scratch (allocation-free rule: __device__ globals)
__device__ float g_sums[KC * DIM];
__device__ int   g_counts[KC];
__device__ float g_J;

// ---------- IEEE helpers (immune to --use_fast_math) ----------
__device__ __forceinline__ float fdiv_rn(float a, float b) {
    float r; asm("div.rn.f32 %0, %1, %2;" : "=f"(r) : "f"(a), "f"(b)); return r;
}
__device__ __forceinline__ float fsqrt_rn(float a) {
    float r; asm("sqrt.rn.f32 %0, %1;" : "=f"(r) : "f"(a)); return r;
}

// ---------- packed f32x2 helpers (sm_100+) ----------
typedef unsigned long long u64;

__device__ __forceinline__ u64 ffma2(u64 a, u64 b, u64 c) {
    u64 r; asm("fma.rn.f32x2 %0, %1, %2, %3;" : "=l"(r) : "l"(a), "l"(b), "l"(c)); return r;
}
__device__ __forceinline__ u64 fmul2(u64 a, u64 b) {
    u64 r; asm("mul.rn.f32x2 %0, %1, %2;" : "=l"(r) : "l"(a), "l"(b)); return r;
}
__device__ __forceinline__ u64 fadd2(u64 a, u64 b) {
    u64 r; asm("add.rn.f32x2 %0, %1, %2;" : "=l"(r) : "l"(a), "l"(b)); return r;
}
__device__ __forceinline__ u64 pack2(float lo, float hi) {
    u64 r; asm("mov.b64 %0, {%1, %2};" : "=l"(r) : "f"(lo), "f"(hi)); return r;
}
__device__ __forceinline__ void unpack2(u64 v, float& lo, float& hi) {
    asm("mov.b64 {%0, %1}, %2;" : "=f"(lo), "=f"(hi) : "l"(v));
}
__device__ __forceinline__ float hsum2(u64 v) {
    float lo, hi; unpack2(v, lo, hi); return lo + hi;
}

// ---------- kernel 0: zero global scratch ----------
__global__ void ck_zero_kernel() {
    int i = blockIdx.x * blockDim.x + threadIdx.x;
    if (i < KC * DIM) g_sums[i] = 0.0f;
    if (i < KC)       g_counts[i] = 0;
    if (i == 0)       g_J = 0.0f;
}

// Load + L2-normalize one row into packed f32x2 registers
__device__ __forceinline__ void load_norm_row(const float* __restrict__ X,
                                              long long row, u64* x) {
    const ulonglong2* xr = (const ulonglong2*)(X + row * DIM);
    #pragma unroll
    for (int j = 0; j < DIM / 4; j++) {
        ulonglong2 t = xr[j];
        x[2 * j]     = t.x;
        x[2 * j + 1] = t.y;
    }
    u64 aq = 0ull;
    #pragma unroll
    for (int j = 0; j < DIM / 2; j++) aq = ffma2(x[j], x[j], aq);
    float inv = fdiv_rn(1.0f, fmaxf(fsqrt_rn(hsum2(aq)), 1e-12f));
    u64 inv2 = pack2(inv, inv);
    #pragma unroll
    for (int j = 0; j < DIM / 2; j++) x[j] = fmul2(x[j], inv2);
}

// Scatter one normalized point into the block-local swizzled bins
__device__ __forceinline__ void scatter_point(float* sAcc, int* sCnt,
                                              int bk, const u64* x) {
    atomicAdd(&sCnt[bk], 1);
    const int sw = bk & 31;
    float* arow = &sAcc[bk * DIM];
    #pragma unroll
    for (int j = 0; j < DIM / 2; j++) {
        float f0, f1; unpack2(x[j], f0, f1);
        atomicAdd(&arow[(2 * j)     ^ sw], f0);
        atomicAdd(&arow[(2 * j + 1) ^ sw], f1);
    }
}

// ---------- kernel 1: persistent assign (2 points/thread) + local accumulate ----------
__global__ void __launch_bounds__(TPB)
ck_assign_kernel(const float* __restrict__ X,
                 const float* __restrict__ C,
                 float* __restrict__ labels_out,
                 int N) {
    extern __shared__ float smem[];
    float* sC   = smem;                 // [KC*DIM] centroids (64KB)
    float* sAcc = smem + KC * DIM;      // [KC*DIM] bins (64KB, XOR-swizzled)
    __shared__ int sCnt[KC];

    const int tid = threadIdx.x;

    // Stage centroids + zero local bins
    {
        const float4* src = (const float4*)C;
        float4* dstC = (float4*)sC;
        float4* dstA = (float4*)sAcc;
        const float4 z = make_float4(0.f, 0.f, 0.f, 0.f);
        #pragma unroll
        for (int i = tid; i < (KC * DIM) / 4; i += TPB) {
            dstC[i] = src[i];
            dstA[i] = z;
        }
        if (tid < KC) sCnt[tid] = 0;
    }
    __syncthreads();

    float jsum = 0.0f;
    const long long S = (long long)gridDim.x * TPB;   // one "lane stride"

    // Each iteration handles rows r and r+S (register-blocked Mt=2)
    for (long long row = (long long)blockIdx.x * TPB + tid; row < N; row += 2 * S) {
        const long long row1 = row + S;
        const bool v1 = (row1 < N);

        u64 x0[DIM / 2], x1[DIM / 2];
        load_norm_row(X, row, x0);
        if (v1) load_norm_row(X, row1, x1);
        else {
            #pragma unroll
            for (int j = 0; j < DIM / 2; j++) x1[j] = 0ull;
        }

        float best0 = -__int_as_float(0x7f800000), best1 = best0;
        int bk0 = 0, bk1 = 0;

        #pragma unroll 1
        for (int k = 0; k < KC; k++) {
            const ulonglong2* cr = (const ulonglong2*)(sC + k * DIM);
            u64 a0 = 0ull, b0 = 0ull, a1 = 0ull, b1 = 0ull;
            #pragma unroll
            for (int j = 0; j < DIM / 4; j++) {
                ulonglong2 c = cr[j];          // one LDS.128 feeds 4 FFMA2
                a0 = ffma2(x0[2 * j],     c.x, a0);
                b0 = ffma2(x0[2 * j + 1], c.y, b0);
                a1 = ffma2(x1[2 * j],     c.x, a1);
                b1 = ffma2(x1[2 * j + 1], c.y, b1);
            }
            float s0 = hsum2(fadd2(a0, b0));
            float s1 = hsum2(fadd2(a1, b1));
            if (s0 > best0) { best0 = s0; bk0 = k; }   // ascending k == first-max tie-break
            if (s1 > best1) { best1 = s1; bk1 = k; }
        }

        labels_out[row] = (float)bk0;
        jsum += 1.0f - best0;
        scatter_point(sAcc, sCnt, bk0, x0);

        if (v1) {
            labels_out[row1] = (float)bk1;
            jsum += 1.0f - best1;
            scatter_point(sAcc, sCnt, bk1, x1);
        }
    }

    // mean_J partial: warp reduce, one global atomic per warp
    #pragma unroll
    for (int o = 16; o > 0; o >>= 1)
        jsum += __shfl_xor_sync(0xffffffffu, jsum, o);
    if ((tid & 31) == 0) atomicAdd(&g_J, jsum);

    __syncthreads();

    // Flush local bins (un-swizzle): 16384 + 256 REDs per block
    for (int i = tid; i < KC * DIM; i += TPB) {
        int k = i >> 6, js = i & 63;
        atomicAdd(&g_sums[(k << 6) + (js ^ (k & 31))], sAcc[i]);
    }
    if (tid < KC && sCnt[tid] > 0) atomicAdd(&g_counts[tid], sCnt[tid]);
}

// ---------- kernel 2: finalize centroids + mean_J ----------
__global__ void ck_finalize_kernel(const float* __restrict__ C,
                                   float* __restrict__ out,   // [KC*DIM] C_new
                                   int N) {
    int k = threadIdx.x;   // 256 threads, one per cluster
    float cnt = (float)g_counts[k];
    bool non_empty = (cnt > 0.0f);
    float safe = fmaxf(cnt, 1.0f);

    float m[DIM];
    float ss = 0.0f;
    #pragma unroll
    for (int j = 0; j < DIM; j++) {
        m[j] = fdiv_rn(g_sums[k * DIM + j], safe);
        ss = fmaf(m[j], m[j], ss);
    }
    float nrm = fmaxf(fsqrt_rn(ss), 1e-12f);
    #pragma unroll
    for (int j = 0; j < DIM; j++)
        out[k * DIM + j] = non_empty ? fdiv_rn(m[j], nrm) : C[k * DIM + j];

    if (k == 0)
        out[(size_t)KC * DIM + (size_t)N] = fdiv_rn(g_J, (float)N);
}

extern "C" void kernel_launch(void* const* d_in, const int* in_sizes, int n_in,
                              void* d_out, int out_size) {
    const float* X = (const float*)d_in[0];
    const float* C = (const float*)d_in[1];
    int N = in_sizes[0] / DIM;

    float* out = (float*)d_out;
    float* labels = out + KC * DIM;   // layout: C_new[16384], labels[N], mean_J[1]

    static const int SMEM = 2 * KC * DIM * sizeof(float);   // 128KB
    cudaFuncSetAttribute(ck_assign_kernel,
                         cudaFuncAttributeMaxDynamicSharedMemorySize, SMEM);

    ck_zero_kernel<<<(KC * DIM + 255) / 256, 256>>>();

    int blocks = (N + TPB - 1) / TPB;
    if (blocks > NBLK) blocks = NBLK;
    ck_assign_kernel<<<blocks, TPB, SMEM>>>(X, C, labels, N);

    ck_finalize_kernel<<<1, KC>>>(C, out, N);
}

// round 4
// speedup vs baseline: 1.1770x; 1.0027x over previous
#include <cuda_runtime.h>
#include <cstdint>

// Cosine K-Means EM step. N=1e6 (from in_sizes), d=64, K=256.
#define KC 256
#define DIM 64
#define TPB 256
#define NBLK 148   // one persistent block per SM (128KB dyn smem/block)

// Scratch (allocation-free rule: __device__ globals)
__device__ float g_sums[KC * DIM];
__device__ int   g_counts[KC];
__device__ float g_J;

// ---------- IEEE helpers (immune to --use_fast_math) ----------
__device__ __forceinline__ float fdiv_rn(float a, float b) {
    float r; asm("div.rn.f32 %0, %1, %2;" : "=f"(r) : "f"(a), "f"(b)); return r;
}
__device__ __forceinline__ float fsqrt_rn(float a) {
    float r; asm("sqrt.rn.f32 %0, %1;" : "=f"(r) : "f"(a)); return r;
}

// ---------- packed f32x2 helpers (sm_100+) ----------
typedef unsigned long long u64;

__device__ __forceinline__ u64 ffma2(u64 a, u64 b, u64 c) {
    u64 r; asm("fma.rn.f32x2 %0, %1, %2, %3;" : "=l"(r) : "l"(a), "l"(b), "l"(c)); return r;
}
__device__ __forceinline__ u64 fmul2(u64 a, u64 b) {
    u64 r; asm("mul.rn.f32x2 %0, %1, %2;" : "=l"(r) : "l"(a), "l"(b)); return r;
}
__device__ __forceinline__ u64 fadd2(u64 a, u64 b) {
    u64 r; asm("add.rn.f32x2 %0, %1, %2;" : "=l"(r) : "l"(a), "l"(b)); return r;
}
__device__ __forceinline__ u64 pack2(float lo, float hi) {
    u64 r; asm("mov.b64 %0, {%1, %2};" : "=l"(r) : "f"(lo), "f"(hi)); return r;
}
__device__ __forceinline__ void unpack2(u64 v, float& lo, float& hi) {
    asm("mov.b64 {%0, %1}, %2;" : "=f"(lo), "=f"(hi) : "l"(v));
}
__device__ __forceinline__ float hsum2(u64 v) {
    float lo, hi; unpack2(v, lo, hi); return lo + hi;
}

// ---------- kernel 0: zero global scratch ----------
__global__ void ck_zero_kernel() {
    int i = blockIdx.x * blockDim.x + threadIdx.x;
    if (i < KC * DIM) g_sums[i] = 0.0f;
    if (i < KC)       g_counts[i] = 0;
    if (i == 0)       g_J = 0.0f;
}

// Load + L2-normalize one row into packed f32x2 registers
__device__ __forceinline__ void load_norm_row(const float* __restrict__ X,
                                              long long row, u64* x) {
    const ulonglong2* xr = (const ulonglong2*)(X + row * DIM);
    #pragma unroll
    for (int j = 0; j < DIM / 4; j++) {
        ulonglong2 t = xr[j];
        x[2 * j]     = t.x;
        x[2 * j + 1] = t.y;
    }
    u64 aq = 0ull;
    #pragma unroll
    for (int j = 0; j < DIM / 2; j++) aq = ffma2(x[j], x[j], aq);
    float inv = fdiv_rn(1.0f, fmaxf(fsqrt_rn(hsum2(aq)), 1e-12f));
    u64 inv2 = pack2(inv, inv);
    #pragma unroll
    for (int j = 0; j < DIM / 2; j++) x[j] = fmul2(x[j], inv2);
}

// Scatter one normalized point into the block-local swizzled bins
__device__ __forceinline__ void scatter_point(float* sAcc, int* sCnt,
                                              int bk, const u64* x) {
    atomicAdd(&sCnt[bk], 1);
    const int sw = bk & 31;
    float* arow = &sAcc[bk * DIM];
    #pragma unroll
    for (int j = 0; j < DIM / 2; j++) {
        float f0, f1; unpack2(x[j], f0, f1);
        atomicAdd(&arow[(2 * j)     ^ sw], f0);
        atomicAdd(&arow[(2 * j + 1) ^ sw], f1);
    }
}

// ---------- kernel 1: persistent assign (2 points/thread) + local accumulate ----------
__global__ void __launch_bounds__(TPB)
ck_assign_kernel(const float* __restrict__ X,
                 const float* __restrict__ C,
                 float* __restrict__ labels_out,
                 int N) {
    extern __shared__ float smem[];
    float* sC   = smem;                 // [KC*DIM] centroids (64KB)
    float* sAcc = smem + KC * DIM;      // [KC*DIM] bins (64KB, XOR-swizzled)
    __shared__ int sCnt[KC];

    const int tid = threadIdx.x;

    // Stage centroids + zero local bins
    {
        const float4* src = (const float4*)C;
        float4* dstC = (float4*)sC;
        float4* dstA = (float4*)sAcc;
        const float4 z = make_float4(0.f, 0.f, 0.f, 0.f);
        #pragma unroll
        for (int i = tid; i < (KC * DIM) / 4; i += TPB) {
            dstC[i] = src[i];
            dstA[i] = z;
        }
        if (tid < KC) sCnt[tid] = 0;
    }
    __syncthreads();

    float jsum = 0.0f;
    const long long S = (long long)gridDim.x * TPB;   // one "lane stride"

    // Each iteration handles rows r and r+S (register-blocked Mt=2)
    for (long long row = (long long)blockIdx.x * TPB + tid; row < N; row += 2 * S) {
        const long long row1 = row + S;
        const bool v1 = (row1 < N);

        u64 x0[DIM / 2], x1[DIM / 2];
        load_norm_row(X, row, x0);
        if (v1) load_norm_row(X, row1, x1);
        else {
            #pragma unroll
            for (int j = 0; j < DIM / 2; j++) x1[j] = 0ull;
        }

        float best0 = -__int_as_float(0x7f800000), best1 = best0;
        int bk0 = 0, bk1 = 0;

        #pragma unroll 1
        for (int k = 0; k < KC; k++) {
            const ulonglong2* cr = (const ulonglong2*)(sC + k * DIM);
            u64 a0 = 0ull, b0 = 0ull, a1 = 0ull, b1 = 0ull;
            #pragma unroll
            for (int j = 0; j < DIM / 4; j++) {
                ulonglong2 c = cr[j];          // one LDS.128 feeds 4 FFMA2
                a0 = ffma2(x0[2 * j],     c.x, a0);
                b0 = ffma2(x0[2 * j + 1], c.y, b0);
                a1 = ffma2(x1[2 * j],     c.x, a1);
                b1 = ffma2(x1[2 * j + 1], c.y, b1);
            }
            float s0 = hsum2(fadd2(a0, b0));
            float s1 = hsum2(fadd2(a1, b1));
            if (s0 > best0) { best0 = s0; bk0 = k; }   // ascending k == first-max tie-break
            if (s1 > best1) { best1 = s1; bk1 = k; }
        }

        labels_out[row] = (float)bk0;
        jsum += 1.0f - best0;
        scatter_point(sAcc, sCnt, bk0, x0);

        if (v1) {
            labels_out[row1] = (float)bk1;
            jsum += 1.0f - best1;
            scatter_point(sAcc, sCnt, bk1, x1);
        }
    }

    // mean_J partial: warp reduce, one global atomic per warp
    #pragma unroll
    for (int o = 16; o > 0; o >>= 1)
        jsum += __shfl_xor_sync(0xffffffffu, jsum, o);
    if ((tid & 31) == 0) atomicAdd(&g_J, jsum);

    __syncthreads();

    // Flush local bins (un-swizzle): 16384 + 256 REDs per block
    for (int i = tid; i < KC * DIM; i += TPB) {
        int k = i >> 6, js = i & 63;
        atomicAdd(&g_sums[(k << 6) + (js ^ (k & 31))], sAcc[i]);
    }
    if (tid < KC && sCnt[tid] > 0) atomicAdd(&g_counts[tid], sCnt[tid]);
}

// ---------- kernel 2: finalize centroids + mean_J ----------
__global__ void ck_finalize_kernel(const float* __restrict__ C,
                                   float* __restrict__ out,   // [KC*DIM] C_new
                                   int N) {
    int k = threadIdx.x;   // 256 threads, one per cluster
    float cnt = (float)g_counts[k];
    bool non_empty = (cnt > 0.0f);
    float safe = fmaxf(cnt, 1.0f);

    float m[DIM];
    float ss = 0.0f;
    #pragma unroll
    for (int j = 0; j < DIM; j++) {
        m[j] = fdiv_rn(g_sums[k * DIM + j], safe);
        ss = fmaf(m[j], m[j], ss);
    }
    float nrm = fmaxf(fsqrt_rn(ss), 1e-12f);
    #pragma unroll
    for (int j = 0; j < DIM; j++)
        out[k * DIM + j] = non_empty ? fdiv_rn(m[j], nrm) : C[k * DIM + j];

    if (k == 0)
        out[(size_t)KC * DIM + (size_t)N] = fdiv_rn(g_J, (float)N);
}

extern "C" void kernel_launch(void* const* d_in, const int* in_sizes, int n_in,
                              void* d_out, int out_size) {
    const float* X = (const float*)d_in[0];
    const float* C = (const float*)d_in[1];
    int N = in_sizes[0] / DIM;

    float* out = (float*)d_out;
    float* labels = out + KC * DIM;   // layout: C_new[16384], labels[N], mean_J[1]

    static const int SMEM = 2 * KC * DIM * sizeof(float);   // 128KB
    cudaFuncSetAttribute(ck_assign_kernel,
                         cudaFuncAttributeMaxDynamicSharedMemorySize, SMEM);

    ck_zero_kernel<<<(KC * DIM + 255) / 256, 256>>>();

    int blocks = (N + TPB - 1) / TPB;
    if (blocks > NBLK) blocks = NBLK;
    ck_assign_kernel<<<blocks, TPB, SMEM>>>(X, C, labels, N);

    ck_finalize_kernel<<<1, KC>>>(C, out, N);
}